// round 12
// baseline (speedup 1.0000x reference)
#include <cuda_runtime.h>

#define N_NODES 100000
#define N_EDGES 1600000

// Scratch (__device__ globals; zero-initialized at load; k_final re-zeroes
// g_deg/g_agg so the invariant holds for every call -> deterministic)
__device__ float  g_deg[N_NODES];
__device__ float  g_dis[N_NODES];
__device__ float2 g_y[N_NODES];        // y[n] = dis[n] * x[n]
__device__ float2 g_agg[N_NODES];      // layer-1 raw scatter target
__device__ float  g_t[N_NODES];        // t[n] = dis[n] * s[n]

// v2 float reduction (one L2 sector instead of two)
__device__ __forceinline__ void red_add_v2(float2* addr, float a, float b) {
    asm volatile("red.global.add.v2.f32 [%0], {%1, %2};"
                 :: "l"(addr), "f"(a), "f"(b) : "memory");
}

// ---- packed f32x2 helpers (sm_103a; FFMA2 is PTX-only, never auto-fused).
// Packed pairs carried as unsigned long long ("l" = 64-bit integer constraint).
typedef unsigned long long u64;
__device__ __forceinline__ u64 ffma2(u64 a, u64 b, u64 c) {
    u64 d;
    asm("fma.rn.f32x2 %0, %1, %2, %3;" : "=l"(d) : "l"(a), "l"(b), "l"(c));
    return d;
}
__device__ __forceinline__ u64 pack2(float lo, float hi) {
    u64 d;
    asm("mov.b64 %0, {%1, %2};" : "=l"(d) : "f"(lo), "f"(hi));
    return d;
}
__device__ __forceinline__ void unpack2(u64 d, float& lo, float& hi) {
    asm("mov.b64 {%0, %1}, %2;" : "=f"(lo), "=f"(hi) : "l"(d));
}

// ---------------------------------------------------------------------------
// K1: degree of target nodes (4 edges/thread, int4 stream)
__global__ void __launch_bounds__(256) k_deg(const int4* __restrict__ col4) {
    int i = blockIdx.x * blockDim.x + threadIdx.x;
    if (i < N_EDGES / 4) {
        int4 c = col4[i];
        atomicAdd(&g_deg[c.x], 1.0f);
        atomicAdd(&g_deg[c.y], 1.0f);
        atomicAdd(&g_deg[c.z], 1.0f);
        atomicAdd(&g_deg[c.w], 1.0f);
    }
}

// K2: dis = deg^-1/2 (0 if deg==0);  y[n] = dis[n]*x[n];  zero out[]
__global__ void __launch_bounds__(256) k_dis(const float* __restrict__ x,
                                             float* __restrict__ out) {
    int n = blockIdx.x * blockDim.x + threadIdx.x;
    if (n < N_NODES) {
        float d   = g_deg[n];
        float dis = (d > 0.0f) ? rsqrtf(d) : 0.0f;
        g_dis[n]  = dis;
        float2 xv = ((const float2*)x)[n];
        g_y[n]    = make_float2(dis * xv.x, dis * xv.y);
        out[n]    = 0.0f;
    }
}

// K3: layer-1 edge scatter: agg_raw[c] += y[r]  (4 edges/thread, batched gathers)
__global__ void __launch_bounds__(256) k_edge1(const int4* __restrict__ row4,
                                               const int4* __restrict__ col4) {
    int i = blockIdx.x * blockDim.x + threadIdx.x;
    if (i < N_EDGES / 4) {
        int4 r = row4[i];
        int4 c = col4[i];
        float2 y0 = g_y[r.x];
        float2 y1 = g_y[r.y];
        float2 y2 = g_y[r.z];
        float2 y3 = g_y[r.w];
        red_add_v2(&g_agg[c.x], y0.x, y0.y);
        red_add_v2(&g_agg[c.y], y1.x, y1.y);
        red_add_v2(&g_agg[c.z], y2.x, y2.y);
        red_add_v2(&g_agg[c.w], y3.x, y3.y);
    }
}

// K4: per-node MLP middle — 2 adjacent nodes/thread, SoA weight arrays
//     (LDS.64 -> naturally packed feature pairs), packed fma.rn.f32x2 math.
//   s[n] = sum_f relu(a0*W1a[f] + a1*W1b[f] + b1[f]) * W2[f];  t[n] = dis*s
__global__ void __launch_bounds__(128) k_nodemid(const float* __restrict__ W1,
                                                 const float* __restrict__ b1,
                                                 const float* __restrict__ W2) {
    __shared__ float s_wa[64], s_wb[64], s_bb[64], s_w2[64];
    int t = threadIdx.x;
    int g = blockIdx.x * blockDim.x + t;   // pair index: nodes 2g, 2g+1
    int n0 = 2 * g;

    // Prefetch both nodes' data FIRST (overlaps the weight-load prologue).
    float2 dis2 = make_float2(0.0f, 0.0f);
    float4 ar2  = make_float4(0.0f, 0.0f, 0.0f, 0.0f);
    if (n0 < N_NODES) {
        dis2 = ((const float2*)g_dis)[g];     // dis[2g], dis[2g+1]
        ar2  = ((const float4*)g_agg)[g];     // agg[2g].xy, agg[2g+1].xy
    }
    if (t < 64) {
        s_wa[t] = W1[t];        // W1[0][f]
        s_wb[t] = W1[64 + t];   // W1[1][f]
        s_bb[t] = b1[t];
        s_w2[t] = W2[t];
    }
    __syncthreads();

    if (n0 < N_NODES) {
        // packed broadcast of per-node activations (once, outside the loop)
        u64 a0a0 = pack2(dis2.x * ar2.x, dis2.x * ar2.x);  // node 2g
        u64 a1a1 = pack2(dis2.x * ar2.y, dis2.x * ar2.y);
        u64 c0c0 = pack2(dis2.y * ar2.z, dis2.y * ar2.z);  // node 2g+1
        u64 c1c1 = pack2(dis2.y * ar2.w, dis2.y * ar2.w);

        const u64* wa_d = (const u64*)s_wa;   // (w_f, w_f+1) pairs
        const u64* wb_d = (const u64*)s_wb;
        const u64* bb_d = (const u64*)s_bb;
        const u64* w2_d = (const u64*)s_w2;

        u64 sa = pack2(0.0f, 0.0f);
        u64 sb = pack2(0.0f, 0.0f);
#pragma unroll
        for (int i = 0; i < 32; i++) {         // 2 features per iter
            u64 wa2 = wa_d[i];
            u64 wb2 = wb_d[i];
            u64 bb2 = bb_d[i];
            u64 w22 = w2_d[i];
            u64 ha = ffma2(a1a1, wb2, ffma2(a0a0, wa2, bb2));
            u64 hb = ffma2(c1c1, wb2, ffma2(c0c0, wa2, bb2));
            float ha0, ha1, hb0, hb1;
            unpack2(ha, ha0, ha1);
            unpack2(hb, hb0, hb1);
            u64 ra = pack2(fmaxf(ha0, 0.0f), fmaxf(ha1, 0.0f));
            u64 rb = pack2(fmaxf(hb0, 0.0f), fmaxf(hb1, 0.0f));
            sa = ffma2(ra, w22, sa);
            sb = ffma2(rb, w22, sb);
        }
        float sa0, sa1, sb0, sb1;
        unpack2(sa, sa0, sa1);
        unpack2(sb, sb0, sb1);
        float2 res = make_float2(dis2.x * (sa0 + sa1), dis2.y * (sb0 + sb1));
        ((float2*)g_t)[g] = res;
    }
}

// K5: layer-2 edge scatter: out_raw[c] += t[r]  (4 edges/thread)
__global__ void __launch_bounds__(256) k_edge2(const int4* __restrict__ row4,
                                               const int4* __restrict__ col4,
                                               float* __restrict__ out) {
    int i = blockIdx.x * blockDim.x + threadIdx.x;
    if (i < N_EDGES / 4) {
        int4 r = row4[i];
        int4 c = col4[i];
        float t0 = g_t[r.x];
        float t1 = g_t[r.y];
        float t2 = g_t[r.z];
        float t3 = g_t[r.w];
        atomicAdd(&out[c.x], t0);
        atomicAdd(&out[c.y], t1);
        atomicAdd(&out[c.z], t2);
        atomicAdd(&out[c.w], t3);
    }
}

// K6: out = relu(dis[n]*out_raw + b2); re-zero deg/agg for next call
__global__ void __launch_bounds__(256) k_final(float* __restrict__ out,
                                               const float* __restrict__ b2) {
    int n = blockIdx.x * blockDim.x + threadIdx.x;
    if (n < N_NODES) {
        out[n] = fmaxf(fmaf(g_dis[n], out[n], b2[0]), 0.0f);
        g_deg[n] = 0.0f;
        g_agg[n] = make_float2(0.0f, 0.0f);
    }
}

// ---------------------------------------------------------------------------
extern "C" void kernel_launch(void* const* d_in, const int* in_sizes, int n_in,
                              void* d_out, int out_size) {
    const float* x  = (const float*)d_in[0];   // [N,2] f32
    const int*   ei = (const int*)d_in[1];     // [2,E] int32 (JAX x64 off)
    const float* W1 = (const float*)d_in[2];   // [2,64]
    const float* b1 = (const float*)d_in[3];   // [64]
    const float* W2 = (const float*)d_in[4];   // [64,1]
    const float* b2 = (const float*)d_in[5];   // [1]
    float*       out = (float*)d_out;          // [N,1]

    const int4* row4 = (const int4*)ei;               // source
    const int4* col4 = (const int4*)(ei + N_EDGES);   // target

    const int BT = 256;
    const int nodeBlocks  = (N_NODES + BT - 1) / BT;
    const int edgeBlocks4 = (N_EDGES / 4 + BT - 1) / BT;
    const int pairBlocks  = (N_NODES / 2 + 127) / 128;   // 2 nodes/thread, BT=128

    k_deg    <<<edgeBlocks4, BT>>>(col4);
    k_dis    <<<nodeBlocks, BT>>>(x, out);
    k_edge1  <<<edgeBlocks4, BT>>>(row4, col4);
    k_nodemid<<<pairBlocks, 128>>>(W1, b1, W2);
    k_edge2  <<<edgeBlocks4, BT>>>(row4, col4, out);
    k_final  <<<nodeBlocks, BT>>>(out, b2);
}

// round 13
// speedup vs baseline: 1.0081x; 1.0081x over previous
#include <cuda_runtime.h>

#define N_NODES 100000
#define N_EDGES 1600000

// Scratch (__device__ globals; zero-initialized at load; k_final re-zeroes
// g_deg/g_agg so the invariant holds for every call -> deterministic)
__device__ float  g_deg[N_NODES];
__device__ float  g_dis[N_NODES];
__device__ float2 g_y[N_NODES];        // y[n] = dis[n] * x[n]
__device__ float2 g_agg[N_NODES];      // layer-1 raw scatter target
__device__ float  g_t[N_NODES];        // t[n] = dis[n] * s[n]

// v2 float reduction (one L2 sector instead of two)
__device__ __forceinline__ void red_add_v2(float2* addr, float a, float b) {
    asm volatile("red.global.add.v2.f32 [%0], {%1, %2};"
                 :: "l"(addr), "f"(a), "f"(b) : "memory");
}

// ---- packed f32x2 helpers (sm_103a; FFMA2 is PTX-only, never auto-fused).
// Packed pairs carried as unsigned long long ("l" = 64-bit integer constraint).
typedef unsigned long long u64;
__device__ __forceinline__ u64 ffma2(u64 a, u64 b, u64 c) {
    u64 d;
    asm("fma.rn.f32x2 %0, %1, %2, %3;" : "=l"(d) : "l"(a), "l"(b), "l"(c));
    return d;
}
__device__ __forceinline__ u64 pack2(float lo, float hi) {
    u64 d;
    asm("mov.b64 %0, {%1, %2};" : "=l"(d) : "f"(lo), "f"(hi));
    return d;
}
__device__ __forceinline__ void unpack2(u64 d, float& lo, float& hi) {
    asm("mov.b64 {%0, %1}, %2;" : "=f"(lo), "=f"(hi) : "l"(d));
}

// ---------------------------------------------------------------------------
// K1: degree of target nodes (4 edges/thread, int4 stream)
__global__ void __launch_bounds__(256) k_deg(const int4* __restrict__ col4) {
    int i = blockIdx.x * blockDim.x + threadIdx.x;
    if (i < N_EDGES / 4) {
        int4 c = col4[i];
        atomicAdd(&g_deg[c.x], 1.0f);
        atomicAdd(&g_deg[c.y], 1.0f);
        atomicAdd(&g_deg[c.z], 1.0f);
        atomicAdd(&g_deg[c.w], 1.0f);
    }
}

// K2: dis = deg^-1/2 (0 if deg==0);  y[n] = dis[n]*x[n];  zero out[]
__global__ void __launch_bounds__(256) k_dis(const float* __restrict__ x,
                                             float* __restrict__ out) {
    int n = blockIdx.x * blockDim.x + threadIdx.x;
    if (n < N_NODES) {
        float d   = g_deg[n];
        float dis = (d > 0.0f) ? rsqrtf(d) : 0.0f;
        g_dis[n]  = dis;
        float2 xv = ((const float2*)x)[n];
        g_y[n]    = make_float2(dis * xv.x, dis * xv.y);
        out[n]    = 0.0f;
    }
}

// K3: layer-1 edge scatter: agg_raw[c] += y[r]  (4 edges/thread, batched gathers)
__global__ void __launch_bounds__(256) k_edge1(const int4* __restrict__ row4,
                                               const int4* __restrict__ col4) {
    int i = blockIdx.x * blockDim.x + threadIdx.x;
    if (i < N_EDGES / 4) {
        int4 r = row4[i];
        int4 c = col4[i];
        float2 y0 = g_y[r.x];
        float2 y1 = g_y[r.y];
        float2 y2 = g_y[r.z];
        float2 y3 = g_y[r.w];
        red_add_v2(&g_agg[c.x], y0.x, y0.y);
        red_add_v2(&g_agg[c.y], y1.x, y1.y);
        red_add_v2(&g_agg[c.z], y2.x, y2.y);
        red_add_v2(&g_agg[c.w], y3.x, y3.y);
    }
}

// K4: per-node MLP middle — 2 adjacent nodes/thread, SoA weight arrays
//     (LDS.64 -> naturally packed feature pairs), packed fma.rn.f32x2 math.
//   s[n] = sum_f relu(a0*W1a[f] + a1*W1b[f] + b1[f]) * W2[f];  t[n] = dis*s
__global__ void __launch_bounds__(128) k_nodemid(const float* __restrict__ W1,
                                                 const float* __restrict__ b1,
                                                 const float* __restrict__ W2) {
    __shared__ float s_wa[64], s_wb[64], s_bb[64], s_w2[64];
    int t = threadIdx.x;
    int g = blockIdx.x * blockDim.x + t;   // pair index: nodes 2g, 2g+1
    int n0 = 2 * g;

    // Prefetch both nodes' data FIRST (overlaps the weight-load prologue).
    float2 dis2 = make_float2(0.0f, 0.0f);
    float4 ar2  = make_float4(0.0f, 0.0f, 0.0f, 0.0f);
    if (n0 < N_NODES) {
        dis2 = ((const float2*)g_dis)[g];     // dis[2g], dis[2g+1]
        ar2  = ((const float4*)g_agg)[g];     // agg[2g].xy, agg[2g+1].xy
    }
    if (t < 64) {
        s_wa[t] = W1[t];        // W1[0][f]
        s_wb[t] = W1[64 + t];   // W1[1][f]
        s_bb[t] = b1[t];
        s_w2[t] = W2[t];
    }
    __syncthreads();

    if (n0 < N_NODES) {
        // packed broadcast of per-node activations (once, outside the loop)
        u64 a0a0 = pack2(dis2.x * ar2.x, dis2.x * ar2.x);  // node 2g
        u64 a1a1 = pack2(dis2.x * ar2.y, dis2.x * ar2.y);
        u64 c0c0 = pack2(dis2.y * ar2.z, dis2.y * ar2.z);  // node 2g+1
        u64 c1c1 = pack2(dis2.y * ar2.w, dis2.y * ar2.w);

        const u64* wa_d = (const u64*)s_wa;   // (w_f, w_f+1) pairs
        const u64* wb_d = (const u64*)s_wb;
        const u64* bb_d = (const u64*)s_bb;
        const u64* w2_d = (const u64*)s_w2;

        u64 sa = pack2(0.0f, 0.0f);
        u64 sb = pack2(0.0f, 0.0f);
#pragma unroll
        for (int i = 0; i < 32; i++) {         // 2 features per iter
            u64 wa2 = wa_d[i];
            u64 wb2 = wb_d[i];
            u64 bb2 = bb_d[i];
            u64 w22 = w2_d[i];
            u64 ha = ffma2(a1a1, wb2, ffma2(a0a0, wa2, bb2));
            u64 hb = ffma2(c1c1, wb2, ffma2(c0c0, wa2, bb2));
            float ha0, ha1, hb0, hb1;
            unpack2(ha, ha0, ha1);
            unpack2(hb, hb0, hb1);
            u64 ra = pack2(fmaxf(ha0, 0.0f), fmaxf(ha1, 0.0f));
            u64 rb = pack2(fmaxf(hb0, 0.0f), fmaxf(hb1, 0.0f));
            sa = ffma2(ra, w22, sa);
            sb = ffma2(rb, w22, sb);
        }
        float sa0, sa1, sb0, sb1;
        unpack2(sa, sa0, sa1);
        unpack2(sb, sb0, sb1);
        float2 res = make_float2(dis2.x * (sa0 + sa1), dis2.y * (sb0 + sb1));
        ((float2*)g_t)[g] = res;
    }
}

// K5: layer-2 edge scatter: out_raw[c] += t[r]  (4 edges/thread)
__global__ void __launch_bounds__(256) k_edge2(const int4* __restrict__ row4,
                                               const int4* __restrict__ col4,
                                               float* __restrict__ out) {
    int i = blockIdx.x * blockDim.x + threadIdx.x;
    if (i < N_EDGES / 4) {
        int4 r = row4[i];
        int4 c = col4[i];
        float t0 = g_t[r.x];
        float t1 = g_t[r.y];
        float t2 = g_t[r.z];
        float t3 = g_t[r.w];
        atomicAdd(&out[c.x], t0);
        atomicAdd(&out[c.y], t1);
        atomicAdd(&out[c.z], t2);
        atomicAdd(&out[c.w], t3);
    }
}

// K6: out = relu(dis[n]*out_raw + b2); re-zero deg/agg for next call
__global__ void __launch_bounds__(256) k_final(float* __restrict__ out,
                                               const float* __restrict__ b2) {
    int n = blockIdx.x * blockDim.x + threadIdx.x;
    if (n < N_NODES) {
        out[n] = fmaxf(fmaf(g_dis[n], out[n], b2[0]), 0.0f);
        g_deg[n] = 0.0f;
        g_agg[n] = make_float2(0.0f, 0.0f);
    }
}

// ---------------------------------------------------------------------------
extern "C" void kernel_launch(void* const* d_in, const int* in_sizes, int n_in,
                              void* d_out, int out_size) {
    const float* x  = (const float*)d_in[0];   // [N,2] f32
    const int*   ei = (const int*)d_in[1];     // [2,E] int32 (JAX x64 off)
    const float* W1 = (const float*)d_in[2];   // [2,64]
    const float* b1 = (const float*)d_in[3];   // [64]
    const float* W2 = (const float*)d_in[4];   // [64,1]
    const float* b2 = (const float*)d_in[5];   // [1]
    float*       out = (float*)d_out;          // [N,1]

    const int4* row4 = (const int4*)ei;               // source
    const int4* col4 = (const int4*)(ei + N_EDGES);   // target

    const int BT = 256;
    const int nodeBlocks  = (N_NODES + BT - 1) / BT;
    const int edgeBlocks4 = (N_EDGES / 4 + BT - 1) / BT;
    const int pairBlocks  = (N_NODES / 2 + 127) / 128;   // 2 nodes/thread, BT=128

    k_deg    <<<edgeBlocks4, BT>>>(col4);
    k_dis    <<<nodeBlocks, BT>>>(x, out);
    k_edge1  <<<edgeBlocks4, BT>>>(row4, col4);
    k_nodemid<<<pairBlocks, 128>>>(W1, b1, W2);
    k_edge2  <<<edgeBlocks4, BT>>>(row4, col4, out);
    k_final  <<<nodeBlocks, BT>>>(out, b2);
}

// round 14
// speedup vs baseline: 1.0915x; 1.0827x over previous
#include <cuda_runtime.h>

#define N_NODES 100000
#define N_EDGES 1600000

// Scratch (__device__ globals; zero-initialized at load; k_final re-zeroes
// g_deg/g_agg so the invariant holds for every call -> deterministic)
__device__ float  g_deg[N_NODES];
__device__ float  g_dis[N_NODES];
__device__ float2 g_y[N_NODES];        // y[n] = dis[n] * x[n]
__device__ float2 g_agg[N_NODES];      // layer-1 raw scatter target
__device__ float  g_t[N_NODES];        // t[n] = dis[n] * s[n]

// v2 float reduction (one L2 sector instead of two)
__device__ __forceinline__ void red_add_v2(float2* addr, float a, float b) {
    asm volatile("red.global.add.v2.f32 [%0], {%1, %2};"
                 :: "l"(addr), "f"(a), "f"(b) : "memory");
}

// ---------------------------------------------------------------------------
// K1: degree of target nodes (4 edges/thread, int4 stream). First kernel —
// launched normally.
__global__ void __launch_bounds__(256) k_deg(const int4* __restrict__ col4) {
    int i = blockIdx.x * blockDim.x + threadIdx.x;
    if (i < N_EDGES / 4) {
        int4 c = col4[i];
        atomicAdd(&g_deg[c.x], 1.0f);
        atomicAdd(&g_deg[c.y], 1.0f);
        atomicAdd(&g_deg[c.z], 1.0f);
        atomicAdd(&g_deg[c.w], 1.0f);
    }
}

// K2: dis = deg^-1/2; y[n] = dis[n]*x[n]; zero out[].
// PDL: x is a harness input -> load before gridsync (overlaps k_deg tail).
__global__ void __launch_bounds__(256) k_dis(const float* __restrict__ x,
                                             float* __restrict__ out) {
    int n = blockIdx.x * blockDim.x + threadIdx.x;
    float2 xv = make_float2(0.0f, 0.0f);
    if (n < N_NODES) xv = ((const float2*)x)[n];   // input-only prefetch
    cudaGridDependencySynchronize();               // wait: k_deg complete
    if (n < N_NODES) {
        float d   = g_deg[n];
        float dis = (d > 0.0f) ? rsqrtf(d) : 0.0f;
        g_dis[n]  = dis;
        g_y[n]    = make_float2(dis * xv.x, dis * xv.y);
        out[n]    = 0.0f;
    }
}

// K3: layer-1 edge scatter: agg_raw[c] += y[r].
// PDL: edge-index stream is input-only -> loads overlap k_dis.
__global__ void __launch_bounds__(256) k_edge1(const int4* __restrict__ row4,
                                               const int4* __restrict__ col4) {
    int i = blockIdx.x * blockDim.x + threadIdx.x;
    int4 r = make_int4(0, 0, 0, 0), c = make_int4(0, 0, 0, 0);
    bool act = i < N_EDGES / 4;
    if (act) { r = row4[i]; c = col4[i]; }         // input-only prefetch
    cudaGridDependencySynchronize();               // wait: k_dis complete
    if (act) {
        float2 y0 = g_y[r.x];
        float2 y1 = g_y[r.y];
        float2 y2 = g_y[r.z];
        float2 y3 = g_y[r.w];
        red_add_v2(&g_agg[c.x], y0.x, y0.y);
        red_add_v2(&g_agg[c.y], y1.x, y1.y);
        red_add_v2(&g_agg[c.z], y2.x, y2.y);
        red_add_v2(&g_agg[c.w], y3.x, y3.y);
    }
}

// K4: per-node MLP middle — 2 adjacent nodes/thread (R10 scalar version).
// PDL: weight loads (inputs) into smem happen before gridsync, overlapping
// k_edge1's tail; node data (g_dis/g_agg, produced upstream) after.
__global__ void __launch_bounds__(128) k_nodemid(const float* __restrict__ W1,
                                                 const float* __restrict__ b1,
                                                 const float* __restrict__ W2) {
    __shared__ float4 s_w[64];   // (W1a, W1b, b1, W2) per feature
    int t = threadIdx.x;
    int g = blockIdx.x * blockDim.x + t;   // pair index: nodes 2g, 2g+1
    int n0 = 2 * g;

    if (t < 64) {
        s_w[t] = make_float4(W1[t], W1[64 + t], b1[t], W2[t]);  // input-only
    }
    cudaGridDependencySynchronize();               // wait: k_edge1 complete

    float2 dis2 = make_float2(0.0f, 0.0f);
    float4 ar2  = make_float4(0.0f, 0.0f, 0.0f, 0.0f);
    if (n0 < N_NODES) {
        dis2 = ((const float2*)g_dis)[g];     // dis[2g], dis[2g+1]
        ar2  = ((const float4*)g_agg)[g];     // agg[2g].xy, agg[2g+1].xy
    }
    __syncthreads();

    if (n0 < N_NODES) {
        float a0 = dis2.x * ar2.x, a1 = dis2.x * ar2.y;   // node 2g
        float c0 = dis2.y * ar2.z, c1 = dis2.y * ar2.w;   // node 2g+1
        float sa0 = 0.0f, sa1 = 0.0f, sb0 = 0.0f, sb1 = 0.0f;
#pragma unroll
        for (int f = 0; f < 64; f += 2) {
            float4 w0 = s_w[f + 0];
            float4 w1 = s_w[f + 1];
            float ha0 = fmaf(a1, w0.y, fmaf(a0, w0.x, w0.z));
            float hb0 = fmaf(c1, w0.y, fmaf(c0, w0.x, w0.z));
            float ha1 = fmaf(a1, w1.y, fmaf(a0, w1.x, w1.z));
            float hb1 = fmaf(c1, w1.y, fmaf(c0, w1.x, w1.z));
            sa0 = fmaf(fmaxf(ha0, 0.0f), w0.w, sa0);
            sb0 = fmaf(fmaxf(hb0, 0.0f), w0.w, sb0);
            sa1 = fmaf(fmaxf(ha1, 0.0f), w1.w, sa1);
            sb1 = fmaf(fmaxf(hb1, 0.0f), w1.w, sb1);
        }
        float2 res = make_float2(dis2.x * (sa0 + sa1), dis2.y * (sb0 + sb1));
        ((float2*)g_t)[g] = res;
    }
}

// K5: layer-2 edge scatter: out_raw[c] += t[r].
__global__ void __launch_bounds__(256) k_edge2(const int4* __restrict__ row4,
                                               const int4* __restrict__ col4,
                                               float* __restrict__ out) {
    int i = blockIdx.x * blockDim.x + threadIdx.x;
    int4 r = make_int4(0, 0, 0, 0), c = make_int4(0, 0, 0, 0);
    bool act = i < N_EDGES / 4;
    if (act) { r = row4[i]; c = col4[i]; }         // input-only prefetch
    cudaGridDependencySynchronize();               // wait: k_nodemid complete
    if (act) {
        float t0 = g_t[r.x];
        float t1 = g_t[r.y];
        float t2 = g_t[r.z];
        float t3 = g_t[r.w];
        atomicAdd(&out[c.x], t0);
        atomicAdd(&out[c.y], t1);
        atomicAdd(&out[c.z], t2);
        atomicAdd(&out[c.w], t3);
    }
}

// K6: out = relu(dis[n]*out_raw + b2); re-zero deg/agg for next call
__global__ void __launch_bounds__(256) k_final(float* __restrict__ out,
                                               const float* __restrict__ b2) {
    int n = blockIdx.x * blockDim.x + threadIdx.x;
    float bias = b2[0];                            // input-only prefetch
    cudaGridDependencySynchronize();               // wait: k_edge2 complete
    if (n < N_NODES) {
        out[n] = fmaxf(fmaf(g_dis[n], out[n], bias), 0.0f);
        g_deg[n] = 0.0f;
        g_agg[n] = make_float2(0.0f, 0.0f);
    }
}

// ---------------------------------------------------------------------------
// PDL launch helper: launch with ProgrammaticStreamSerialization so the kernel
// may start while its stream predecessor is still running; correctness comes
// from cudaGridDependencySynchronize() inside each kernel.
template <typename... Args>
static void launch_pss(void (*kern)(Args...), int grid, int block, Args... args) {
    cudaLaunchConfig_t cfg = {};
    cfg.gridDim  = dim3(grid, 1, 1);
    cfg.blockDim = dim3(block, 1, 1);
    cfg.dynamicSmemBytes = 0;
    cfg.stream = 0;
    cudaLaunchAttribute attr[1];
    attr[0].id = cudaLaunchAttributeProgrammaticStreamSerialization;
    attr[0].val.programmaticStreamSerializationAllowed = 1;
    cfg.attrs = attr;
    cfg.numAttrs = 1;
    cudaLaunchKernelEx(&cfg, kern, args...);
}

extern "C" void kernel_launch(void* const* d_in, const int* in_sizes, int n_in,
                              void* d_out, int out_size) {
    const float* x  = (const float*)d_in[0];   // [N,2] f32
    const int*   ei = (const int*)d_in[1];     // [2,E] int32 (JAX x64 off)
    const float* W1 = (const float*)d_in[2];   // [2,64]
    const float* b1 = (const float*)d_in[3];   // [64]
    const float* W2 = (const float*)d_in[4];   // [64,1]
    const float* b2 = (const float*)d_in[5];   // [1]
    float*       out = (float*)d_out;          // [N,1]

    const int4* row4 = (const int4*)ei;               // source
    const int4* col4 = (const int4*)(ei + N_EDGES);   // target

    const int BT = 256;
    const int nodeBlocks  = (N_NODES + BT - 1) / BT;
    const int edgeBlocks4 = (N_EDGES / 4 + BT - 1) / BT;
    const int pairBlocks  = (N_NODES / 2 + 127) / 128;   // 2 nodes/thread

    k_deg<<<edgeBlocks4, BT>>>(col4);                       // first: normal
    launch_pss(k_dis,     nodeBlocks,  BT,  x, out);
    launch_pss(k_edge1,   edgeBlocks4, BT,  row4, col4);
    launch_pss(k_nodemid, pairBlocks,  128, W1, b1, W2);
    launch_pss(k_edge2,   edgeBlocks4, BT,  row4, col4, out);
    launch_pss(k_final,   nodeBlocks,  BT,  out, b2);
}